// round 16
// baseline (speedup 1.0000x reference)
#include <cuda_runtime.h>
#include <cuda_bf16.h>
#include <math.h>
#include <string.h>

// Problem constants (fixed by the dataset)
#define TT 1024
#define SS 512
#define DD 32
#define KK 64
#define LOG2PI 1.8378770664093453f

// Device-global scratch (no allocations allowed)
__device__ float2 g_pp[KK * DD];        // (-0.5/covar, mean/covar) packed pairs
__device__ float  g_base[KK];           // log-density constant per state
__device__ float  g_dsum[SS * TT];      // per-step denominators
__device__ float  g_logden[SS];         // per-sequence sum log(denom)

// ---- packed fp32x2 helpers (sm_103a) --------------------------------------
__device__ __forceinline__ unsigned long long ffma2(unsigned long long a,
                                                    unsigned long long b,
                                                    unsigned long long c) {
    unsigned long long d;
    asm("fma.rn.f32x2 %0, %1, %2, %3;" : "=l"(d) : "l"(a), "l"(b), "l"(c));
    return d;
}
__device__ __forceinline__ unsigned long long fadd2(unsigned long long a,
                                                    unsigned long long b) {
    unsigned long long d;
    asm("add.rn.f32x2 %0, %1, %2;" : "=l"(d) : "l"(a), "l"(b));
    return d;
}
__device__ __forceinline__ float2 unpack2(unsigned long long a) {
    float2 f;
    asm("mov.b64 {%0, %1}, %2;" : "=f"(f.x), "=f"(f.y) : "l"(a));
    return f;
}
__device__ __forceinline__ float rcp_approx(float x) {
    float y;
    asm("rcp.approx.f32 %0, %1;" : "=f"(y) : "f"(x));
    return y;
}

// Per-sequence named barrier: id in {1,2}, 64 threads (2 warps)
#define BARSEQ(id) asm volatile("bar.sync %0, 64;" :: "r"(id) : "memory")

// ---------------------------------------------------------------------------
// Precompute: warp = one state k, lane = dim d. shfl-reduce the constants.
// ---------------------------------------------------------------------------
__global__ void precompute_kernel(const float* __restrict__ means,
                                  const float* __restrict__ covars) {
    int w = threadIdx.x >> 5;
    int d = threadIdx.x & 31;
    int k = blockIdx.x * 32 + w;
    if (k >= KK) return;
    float c = covars[k * DD + d];
    float m = means [k * DD + d];
    float ic = 1.0f / c;
    g_pp[k * DD + d] = make_float2(-0.5f * ic, m * ic);
    float m2 = m * m * ic;
    float lc = logf(c);
    #pragma unroll
    for (int off = 16; off; off >>= 1) {
        m2 += __shfl_xor_sync(0xffffffffu, m2, off);
        lc += __shfl_xor_sync(0xffffffffu, lc, off);
    }
    if (d == 0) g_base[k] = -0.5f * (m2 + lc + (float)DD * LOG2PI);
}

// ---------------------------------------------------------------------------
// Fused forward kernel: 128-thread block = TWO independent sequences.
//   warps 0-1 (SMSP 0,1) run sequence 2*bid;  warps 2-3 (SMSP 2,3) run
//   sequence 2*bid+1 — fills all four schedulers (wid%4 -> SMSP mapping).
//   Per-sequence sync via named barrier (bar.sync 1+ls, 64).
// Per step, per sequence: ONE named barrier, NO reduction tree:
//   - dsum_{t-1} computed by every thread from the same shared alpha operands
//     the transition dot already loads (piggyback fadd2, overlaps the dot)
//   - rcp.approx on the normalization (error cancels across renormalization)
//   - branch-free x staging with clamped prefetch index
//   - ordering acc = p * (dot * rcp(dsum)) is underflow-safe
// ---------------------------------------------------------------------------
__global__ __launch_bounds__(128) void hmm_forward_kernel(
    const float* __restrict__ data,      // [T, S, D]
    const float* __restrict__ initp,     // [K]
    const float* __restrict__ A,         // [K, K]
    float* __restrict__ out)             // [S, K]
{
    const int tid  = threadIdx.x;
    const int ls   = tid >> 6;           // local sequence 0/1
    const int k    = tid & 63;           // state
    const int lane = tid & 31;
    const int wrp  = (tid >> 5) & 1;     // warp within sequence
    const int s    = blockIdx.x * 2 + ls;
    const int bar  = 1 + ls;

    __shared__ __align__(16) float  acc_sh[2][2][KK];  // [ls][buf][k]
    __shared__ __align__(16) float2 xsh[2][2][DD];     // [ls][buf][d]
    __shared__ float red_sh[2][2];                     // [ls][warp] epilogue

    // Packed emission params for state k: pp[d] = (-0.5/c_d, m_d/c_d)
    unsigned long long pp[DD];
    {
        const ulonglong2* p2 = reinterpret_cast<const ulonglong2*>(&g_pp[k * DD]);
        #pragma unroll
        for (int i = 0; i < DD / 2; i++) {
            ulonglong2 v = p2[i];
            pp[2 * i] = v.x; pp[2 * i + 1] = v.y;
        }
    }
    const float base  = g_base[k];
    const float initk = __ldg(&initp[k]);

    // Packed A column: Ac[j] = (A[2j][k], A[2j+1][k])
    unsigned long long Ac[KK / 2];
    #pragma unroll
    for (int j = 0; j < KK / 2; j++) {
        float2 f = make_float2(__ldg(&A[(2 * j) * KK + k]),
                               __ldg(&A[(2 * j + 1) * KK + k]));
        unsigned long long u; memcpy(&u, &f, 8);
        Ac[j] = u;
    }

    // x staging: both warps of the sequence, 16 dims each
    const bool stager = (lane < 16);
    const int  d_my   = wrp * 16 + lane;            // valid when stager
    const float* dptr = data + (size_t)s * DD;      // data[(t*S+s)*D + d]
    float xn = 0.0f;
    if (stager) {
        float x0 = __ldg(dptr + d_my);
        float x1 = __ldg(dptr + (size_t)1 * SS * DD + d_my);
        xsh[ls][0][d_my] = make_float2(x0 * x0, x0);
        xsh[ls][1][d_my] = make_float2(x1 * x1, x1);
        xn               = __ldg(dptr + (size_t)2 * SS * DD + d_my);
    }
    __syncthreads();    // whole-block once; per-step barriers are per-sequence

    // Emission: logp = base + sum_d (x^2,x).(ninv,miv); 32 FFMA2
    auto emission = [&](int buf) -> float {
        const ulonglong2* xr = reinterpret_cast<const ulonglong2*>(xsh[ls][buf]);
        unsigned long long a0 = 0ull, a1 = 0ull, a2 = 0ull, a3 = 0ull;
        #pragma unroll
        for (int i = 0; i < DD / 4; i += 2) {
            ulonglong2 v0 = xr[2 * i];
            ulonglong2 v1 = xr[2 * i + 1];
            ulonglong2 v2 = xr[2 * i + 2];
            ulonglong2 v3 = xr[2 * i + 3];
            a0 = ffma2(v0.x, pp[4 * i + 0], a0);
            a1 = ffma2(v0.y, pp[4 * i + 1], a1);
            a2 = ffma2(v1.x, pp[4 * i + 2], a2);
            a3 = ffma2(v1.y, pp[4 * i + 3], a3);
            a0 = ffma2(v2.x, pp[4 * i + 4], a0);
            a1 = ffma2(v2.y, pp[4 * i + 5], a1);
            a2 = ffma2(v3.x, pp[4 * i + 6], a2);
            a3 = ffma2(v3.y, pp[4 * i + 7], a3);
        }
        float2 f = unpack2(fadd2(fadd2(a0, a1), fadd2(a2, a3)));
        return __expf(base + f.x + f.y);
    };

    // ---- t = 0 ---- (dsum_0 computed by the piggyback sum in step 1)
    float acc = initk * emission(0);
    acc_sh[ls][0][k] = acc;
    BARSEQ(bar);

    float* dsum_out = g_dsum + (size_t)s * TT;

    // ---- t = 1 .. TT-1 ----
    #pragma unroll 2
    for (int t = 1; t < TT; t++) {
        const int cb = t & 1;
        const int pb = cb ^ 1;

        // Branch-free staging: store (x^2,x) for t+1; prefetch clamped t+2
        if (stager) {
            xsh[ls][pb][d_my] = make_float2(xn * xn, xn);
            int t2 = (t + 2 < TT) ? (t + 2) : (TT - 1);
            xn = __ldg(dptr + (size_t)t2 * SS * DD + d_my);
        }

        // Transition dot (32 FFMA2) + piggyback dsum (32 fadd2) over the SAME
        // broadcast LDS.128 operands.
        const ulonglong2* a2p = reinterpret_cast<const ulonglong2*>(acc_sh[ls][pb]);
        unsigned long long q0 = 0ull, q1 = 0ull, q2 = 0ull, q3 = 0ull;
        unsigned long long u0 = 0ull, u1 = 0ull, u2 = 0ull, u3 = 0ull;
        #pragma unroll
        for (int jj = 0; jj < 16; jj += 2) {
            ulonglong2 v0 = a2p[jj];
            ulonglong2 v1 = a2p[jj + 1];
            q0 = ffma2(v0.x, Ac[2 * jj + 0], q0);
            q1 = ffma2(v0.y, Ac[2 * jj + 1], q1);
            q2 = ffma2(v1.x, Ac[2 * jj + 2], q2);
            q3 = ffma2(v1.y, Ac[2 * jj + 3], q3);
            u0 = fadd2(u0, v0.x);
            u1 = fadd2(u1, v0.y);
            u2 = fadd2(u2, v1.x);
            u3 = fadd2(u3, v1.y);
        }
        float2 fq = unpack2(fadd2(fadd2(q0, q1), fadd2(q2, q3)));
        float2 fu = unpack2(fadd2(fadd2(u0, u1), fadd2(u2, u3)));
        float dsum = fu.x + fu.y;
        float r = rcp_approx(dsum);
        if (k == 0) dsum_out[t - 1] = dsum;     // fire-and-forget (exact dsum)

        float dotn = (fq.x + fq.y) * r;         // rescale BEFORE p (underflow-safe)
        float p = emission(cb);
        acc = p * dotn;
        acc_sh[ls][cb][k] = acc;

        BARSEQ(bar);
    }

    // Epilogue: one reduction tree for dsum_{TT-1}, then final normalization
    {
        float v = acc;
        #pragma unroll
        for (int off = 16; off; off >>= 1)
            v += __shfl_xor_sync(0xffffffffu, v, off);
        if (lane == 0) red_sh[ls][wrp] = v;
        BARSEQ(bar);
        float dsum = red_sh[ls][0] + red_sh[ls][1];
        float r = 1.0f / dsum;                   // exact, off the hot path
        out[(size_t)s * KK + k] = acc * r;
        if (k == 0) dsum_out[TT - 1] = dsum;
    }
}

// ---------------------------------------------------------------------------
// Parallel log-sum over t: one block per sequence, fixed-order tree reduce.
// ---------------------------------------------------------------------------
__global__ void logsum_kernel() {
    __shared__ float sh[256];
    const int s = blockIdx.x;
    const int tid = threadIdx.x;
    const float* ds = g_dsum + (size_t)s * TT;
    float acc = 0.0f;
    #pragma unroll
    for (int i = 0; i < TT / 256; i++)
        acc += __logf(ds[i * 256 + tid]);
    sh[tid] = acc;
    __syncthreads();
    #pragma unroll
    for (int off = 128; off > 0; off >>= 1) {
        if (tid < off) sh[tid] += sh[tid + off];
        __syncthreads();
    }
    if (tid == 0) g_logden[s] = sh[0];
}

// ---------------------------------------------------------------------------
// Deterministic reduction over sequences -> -log_likelihood
// ---------------------------------------------------------------------------
__global__ void finalize_kernel(float* __restrict__ out, int out_size) {
    __shared__ float sh[SS];
    int tid = threadIdx.x;
    sh[tid] = g_logden[tid];
    __syncthreads();
    #pragma unroll
    for (int off = SS / 2; off > 0; off >>= 1) {
        if (tid < off) sh[tid] += sh[tid + off];
        __syncthreads();
    }
    if (tid == 0 && out_size > SS * KK) {
        out[out_size - 1] = -sh[0];
    }
}

extern "C" void kernel_launch(void* const* d_in, const int* in_sizes, int n_in,
                              void* d_out, int out_size) {
    const float* data  = (const float*)d_in[0];  // [T,S,D]
    const float* initp = (const float*)d_in[1];  // [K]
    const float* A     = (const float*)d_in[2];  // [K,K]
    const float* means = (const float*)d_in[3];  // [K,D]
    const float* covar = (const float*)d_in[4];  // [K,D]
    float* out = (float*)d_out;

    precompute_kernel<<<2, 1024>>>(means, covar);
    hmm_forward_kernel<<<SS / 2, 128>>>(data, initp, A, out);
    logsum_kernel<<<SS, 256>>>();
    finalize_kernel<<<1, SS>>>(out, out_size);
}